// round 17
// baseline (speedup 1.0000x reference)
#include <cuda_runtime.h>
#include <cuda_bf16.h>
#include <math.h>

// ---------------- problem constants ----------------
#define NNODES 325
#define BATCH  64
#define TSTEPS 12
#define HORIZON 12
#define UNITS  64
#define DIN    2
#define XKSTR  (NNODES*384)
#define NTH    512
#define NWARPS 16
#define SPLIT  192               // rank0 rows [0,192) (=128+64 exact), rank1 [192,325)
#define MAXE   2600
#define WPMAX  32768

typedef unsigned long long ull;
typedef __nv_bfloat16 bf16;

// ---------------- device scratch (A basis = [x,h]; B basis = [x,rh]) ----------------
__device__ __align__(16) float g_xkA[BATCH*XKSTR];
__device__ __align__(16) bf16  g_xhA[BATCH*XKSTR];
__device__ __align__(16) bf16  g_xlA[BATCH*XKSTR];
__device__ __align__(16) float g_xkB[BATCH*XKSTR];
__device__ __align__(16) bf16  g_xhB[BATCH*XKSTR];
__device__ __align__(16) bf16  g_xlB[BATCH*XKSTR];
__device__ float g_h0[BATCH*NNODES*UNITS];
__device__ float g_h1[BATCH*NNODES*UNITS];
__device__ float g_u [BATCH*NNODES*UNITS];
__device__ float g_din[BATCH*NNODES];
__device__ unsigned g_wph[8][WPMAX];
__device__ unsigned g_wpl[8][WPMAX];
__device__ unsigned g_slot[BATCH][2];   // per-rank barrier slots (self-written only)

// ---------------- helpers ----------------
__device__ __forceinline__ void bfsplit(float a, bf16 &h, bf16 &l){
    h = __float2bfloat16(a);
    l = __float2bfloat16(a - __bfloat162float(h));
}
__device__ __forceinline__ void mma16816(float* d, const unsigned* a, const unsigned* b){
    asm volatile("mma.sync.aligned.m16n8k16.row.col.f32.bf16.bf16.f32 "
        "{%0,%1,%2,%3}, {%4,%5,%6,%7}, {%8,%9}, {%0,%1,%2,%3};"
        : "+f"(d[0]), "+f"(d[1]), "+f"(d[2]), "+f"(d[3])
        : "r"(a[0]), "r"(a[1]), "r"(a[2]), "r"(a[3]), "r"(b[0]), "r"(b[1]));
}
// pair barrier (R12 fence structure; slot-based -> no init kernel, replay-safe)
__device__ __forceinline__ void psync(volatile unsigned* my, volatile unsigned* peer,
                                      unsigned &ep){
    __threadfence();
    __syncthreads();
    if (threadIdx.x == 0){
        ep += 1;
        *my = ep;
        while (*peer < ep) { }
    }
    __syncthreads();
    __threadfence();
}

// folded weight: basis [x0, Sx0, SSx0] -> W' = [W0 - W2 ; W1 ; 2*W2] (sections padded to FP)
__device__ __forceinline__ float wmod(const float* W, int F, int FP, int ONUM, int k, int n){
    int sec = k / FP, col = k - sec*FP;
    if (sec > 2 || col >= F) return 0.f;
    if (sec == 0) return W[col*ONUM + n] - W[(2*F + col)*ONUM + n];
    if (sec == 1) return W[(F + col)*ONUM + n];
    return 2.f*W[(2*F + col)*ONUM + n];
}

// ---------------- sparse apply: rows [rbeg,rend), cols [a0,FP); R12 2-wide loop ----------------
template<int FP, int STRR, bool WF32>
__device__ void sp_apply(float* xk, bf16* xh, bf16* xl, int src, int dst, int a0,
                         const ull* s_ent, const int* s_rp, int rbeg, int rend)
{
    const int G = (FP - a0) >> 2;
    const int tasks = (rend - rbeg)*G;
    for (int t = threadIdx.x; t < tasks; t += NTH){
        int m = rbeg + t/G, f = a0 + (t - (t/G)*G)*4;
        const float* sp = xk + src + f;
        float ax = 0.f, ay = 0.f, az = 0.f, aw = 0.f;
        int j = s_rp[m], j1 = s_rp[m+1];
        for (; j + 1 < j1; j += 2){
            ull e0 = s_ent[j], e1 = s_ent[j+1];
            float v0 = __uint_as_float((unsigned)(e0 >> 32));
            float v1 = __uint_as_float((unsigned)(e1 >> 32));
            float4 x0 = *(const float4*)(sp + (int)(unsigned)e0 * STRR);
            float4 x1 = *(const float4*)(sp + (int)(unsigned)e1 * STRR);
            ax += v0*x0.x + v1*x1.x;  ay += v0*x0.y + v1*x1.y;
            az += v0*x0.z + v1*x1.z;  aw += v0*x0.w + v1*x1.w;
        }
        if (j < j1){
            ull e0 = s_ent[j];
            float v0 = __uint_as_float((unsigned)(e0 >> 32));
            float4 x0 = *(const float4*)(sp + (int)(unsigned)e0 * STRR);
            ax += v0*x0.x; ay += v0*x0.y; az += v0*x0.z; aw += v0*x0.w;
        }
        int o = m*STRR + dst + f;
        if (WF32) *(float4*)(xk + o) = make_float4(ax, ay, az, aw);
        bf16 hx,lx,hy,ly,hz,lz,hw,lw;
        bfsplit(ax,hx,lx); bfsplit(ay,hy,ly); bfsplit(az,hz,lz); bfsplit(aw,hw,lw);
        uint2 uh, ul2;
        uh.x  = (unsigned)__bfloat16_as_ushort(hx) | ((unsigned)__bfloat16_as_ushort(hy) << 16);
        uh.y  = (unsigned)__bfloat16_as_ushort(hz) | ((unsigned)__bfloat16_as_ushort(hw) << 16);
        ul2.x = (unsigned)__bfloat16_as_ushort(lx) | ((unsigned)__bfloat16_as_ushort(ly) << 16);
        ul2.y = (unsigned)__bfloat16_as_ushort(lz) | ((unsigned)__bfloat16_as_ushort(lw) << 16);
        *(uint2*)(xh + o) = uh;
        *(uint2*)(xl + o) = ul2;
    }
}

// ---------------- barrier-free mma GEMM chunk (direct-LDG A frags; OWN rows only) ----------------
// SPL: per-k-tile A-source select — (kt&7)<4 -> (xh,xl) [x-part, basis A], else (xh2,xl2) [rh, basis B]
template<int MW, int NW, int ONUM, int FP, int STRR, bool SPL>
__device__ void gemm_chunk(int row0, int rowEnd,
    const bf16* __restrict__ xh, const bf16* __restrict__ xl,
    const bf16* __restrict__ xh2, const bf16* __restrict__ xl2,
    float* xkB, bf16* xhB, bf16* xlB,
    const unsigned* __restrict__ wph, const unsigned* __restrict__ wpl,
    const float* __restrict__ bias, float* H, float* us, int epi, int FX,
    const float* __restrict__ pW, const float* __restrict__ pb,
    float* __restrict__ out_t, float* __restrict__ din, float* s_red)
{
    constexpr int NKT = (3*FP + 15)/16;
    constexpr int NA  = ONUM/(8*NW);
    constexpr int BM  = MW*32;
    const int tid = threadIdx.x, lane = tid & 31, wid = tid >> 5;
    const int mw = wid % MW, nw = wid / MW;
    const int g = lane >> 2, q = lane & 3;

    int aoff[4];
    #pragma unroll
    for (int i = 0; i < 4; i++){
        int r = row0 + mw*32 + i*8 + g;
        if (r > NNODES-1) r = NNODES-1;        // clamp stays within own-rank rows
        aoff[i] = r*STRR + q*2;
    }

    float acc[2][NA][4];
    #pragma unroll
    for (int i = 0; i < 2; i++)
        #pragma unroll
        for (int j = 0; j < NA; j++)
            #pragma unroll
            for (int k = 0; k < 4; k++) acc[i][j][k] = 0.f;

    unsigned aH[2][2][4], aL[2][2][4], bB[2][NA][4];

    auto ldA = [&](int kt, int st){
        int kk = kt*16;
        const bf16* sh = (!SPL || ((kt & 7) < 4)) ? xh : xh2;
        const bf16* sl = (!SPL || ((kt & 7) < 4)) ? xl : xl2;
        #pragma unroll
        for (int ma = 0; ma < 2; ma++){
            aH[st][ma][0] = *(const unsigned*)(sh + aoff[2*ma]   + kk);
            aH[st][ma][1] = *(const unsigned*)(sh + aoff[2*ma+1] + kk);
            aH[st][ma][2] = *(const unsigned*)(sh + aoff[2*ma]   + kk + 8);
            aH[st][ma][3] = *(const unsigned*)(sh + aoff[2*ma+1] + kk + 8);
            aL[st][ma][0] = *(const unsigned*)(sl + aoff[2*ma]   + kk);
            aL[st][ma][1] = *(const unsigned*)(sl + aoff[2*ma+1] + kk);
            aL[st][ma][2] = *(const unsigned*)(sl + aoff[2*ma]   + kk + 8);
            aL[st][ma][3] = *(const unsigned*)(sl + aoff[2*ma+1] + kk + 8);
        }
    };
    auto ldB = [&](int kt, int st){
        #pragma unroll
        for (int na = 0; na < NA; na++){
            int base = (((nw*NA + na)*NKT + kt)*32 + lane)*2;
            uint2 bh = *(const uint2*)(wph + base);
            uint2 bl = *(const uint2*)(wpl + base);
            bB[st][na][0] = bh.x; bB[st][na][1] = bh.y;
            bB[st][na][2] = bl.x; bB[st][na][3] = bl.y;
        }
    };

    ldA(0, 0); ldB(0, 0);
    for (int kt = 0; kt < NKT; kt++){
        int cur = kt & 1, nxt = cur ^ 1;
        if (kt + 1 < NKT){ ldA(kt+1, nxt); ldB(kt+1, nxt); }
        #pragma unroll
        for (int na = 0; na < NA; na++){
            unsigned bh[2] = {bB[cur][na][0], bB[cur][na][1]};
            unsigned bl[2] = {bB[cur][na][2], bB[cur][na][3]};
            #pragma unroll
            for (int ma = 0; ma < 2; ma++){
                mma16816(acc[ma][na], aH[cur][ma], bh);
                mma16816(acc[ma][na], aH[cur][ma], bl);
                mma16816(acc[ma][na], aL[cur][ma], bh);
            }
        }
    }

    float pvp[2][2] = {{0.f,0.f},{0.f,0.f}};
    #pragma unroll
    for (int ma = 0; ma < 2; ma++){
        #pragma unroll
        for (int na = 0; na < NA; na++){
            int n0 = nw*(8*NA) + na*8 + q*2;
            #pragma unroll
            for (int half = 0; half < 2; half++){
                int r = row0 + mw*32 + ma*16 + g + half*8;
                if (r >= rowEnd) continue;
                float v0 = acc[ma][na][half*2 + 0] + bias[n0];
                float v1 = acc[ma][na][half*2 + 1] + bias[n0 + 1];
                if (epi == 0){
                    float s0 = 1.f/(1.f + expf(-v0));
                    float s1 = 1.f/(1.f + expf(-v1));
                    if (n0 < UNITS){
                        float r0 = s0 * H[r*UNITS + n0];
                        float r1 = s1 * H[r*UNITS + n0 + 1];
                        int o = r*STRR + FX + n0;
                        xkB[o] = r0; xkB[o+1] = r1;
                        bf16 h, l;
                        bfsplit(r0, h, l); xhB[o] = h;   xlB[o] = l;
                        bfsplit(r1, h, l); xhB[o+1] = h; xlB[o+1] = l;
                    } else {
                        us[r*UNITS + (n0 - UNITS)]     = s0;
                        us[r*UNITS + (n0 - UNITS) + 1] = s1;
                    }
                } else {
                    float c0 = tanhf(v0), c1 = tanhf(v1);
                    float u0 = us[r*UNITS + n0],     u1 = us[r*UNITS + n0 + 1];
                    float h0v = H[r*UNITS + n0],     h1v = H[r*UNITS + n0 + 1];
                    float hn0 = u0*h0v + (1.f - u0)*c0;
                    float hn1 = u1*h1v + (1.f - u1)*c1;
                    H[r*UNITS + n0]     = hn0;
                    H[r*UNITS + n0 + 1] = hn1;
                    if (epi == 2) pvp[ma][half] += hn0*pW[n0] + hn1*pW[n0 + 1];
                }
            }
        }
    }
    if (epi == 2){
        #pragma unroll
        for (int ma = 0; ma < 2; ma++)
            #pragma unroll
            for (int half = 0; half < 2; half++){
                float v = pvp[ma][half];
                v += __shfl_down_sync(0xffffffffu, v, 2);
                v += __shfl_down_sync(0xffffffffu, v, 1);
                if (q == 0) s_red[(mw*32 + ma*16 + g + half*8)*NW + nw] = v;
            }
        __syncthreads();
        if (tid < BM){
            int r = row0 + tid;
            if (r < rowEnd){
                float v = pb[0];
                #pragma unroll
                for (int w2 = 0; w2 < NW; w2++) v += s_red[tid*NW + w2];
                din[r]  = v;
                out_t[r] = v;
            }
        }
        __syncthreads();
    }
}

// ---------------- one GRU cell (R12 psync structure; SPL = layer-1 x-part reuse) ----------------
template<int FX, int F, int FP, int STRR>
__device__ void cell_run(int b, int rbeg, int rend,
                         const float* __restrict__ xptr, float* H,
                         int matg, int matc,
                         const float* gb, const float* cb, int epi_cand,
                         const float* pW, const float* pb, float* out_t,
                         volatile unsigned* my, volatile unsigned* peer, unsigned &ep,
                         const ull* s_ent, const int* s_rp, float* s_red)
{
    constexpr bool SPL = (FX == UNITS);    // layer-1 cells: cand reads x-part from basis A
    float* xkA = g_xkA + b*XKSTR;  bf16* xhA = g_xhA + b*XKSTR;  bf16* xlA = g_xlA + b*XKSTR;
    float* xkB = g_xkB + b*XKSTR;  bf16* xhB = g_xhB + b*XKSTR;  bf16* xlB = g_xlB + b*XKSTR;
    float* us  = g_u   + b*NNODES*UNITS;
    float* din = g_din + b*NNODES;

    __syncthreads();   // prev-cell H/din (own-CTA cross-warp)
    // concat own rows: A.x0 = [x, h] + pads ; B.x0 x-cols (skipped when SPL)
    for (int idx = threadIdx.x; idx < (rend - rbeg)*FP; idx += NTH){
        int m = rbeg + idx/FP, f = idx - (idx/FP)*FP;
        int o = m*STRR + f;
        float v;
        bf16 h, l;
        if (f >= F){
            xkA[o] = 0.f; xhA[o] = __float2bfloat16(0.f); xlA[o] = __float2bfloat16(0.f);
            if (!SPL){ xkB[o] = 0.f; xhB[o] = __float2bfloat16(0.f); xlB[o] = __float2bfloat16(0.f); }
            continue;
        }
        if (f < FX){
            v = (FX == 2) ? xptr[m*DIN + f] : ((FX == 1) ? xptr[m] : xptr[m*UNITS + f]);
            bfsplit(v, h, l);
            xkA[o] = v; xhA[o] = h; xlA[o] = l;
            if (!SPL){ xkB[o] = v; xhB[o] = h; xlB[o] = l; }
        } else {
            v = H[m*UNITS + (f - FX)];
            bfsplit(v, h, l);
            xkA[o] = v; xhA[o] = h; xlA[o] = l;
        }
    }
    psync(my, peer, ep);                                               // (a) x0 all rows ready
    sp_apply<FP,STRR,true >(xkA, xhA, xlA, 0,  FP,   0, s_ent, s_rp, rbeg, rend);  // A: S x0
    psync(my, peer, ep);                                               // (b) x1 all rows ready
    sp_apply<FP,STRR,false>(xkA, xhA, xlA, FP, 2*FP, 0, s_ent, s_rp, rbeg, rend);  // A: S x1
    __syncthreads();                                                   // own rows only below
    gemm_chunk<4,4,128,FP,STRR,false>(rbeg,       rend, xhA, xlA, xhA, xlA, xkB, xhB, xlB,
        g_wph[matg], g_wpl[matg], gb, H, us, 0, FX, nullptr, nullptr, nullptr, din, s_red);
    gemm_chunk<2,8,128,FP,STRR,false>(rbeg + 128, rend, xhA, xlA, xhA, xlA, xkB, xhB, xlB,
        g_wph[matg], g_wpl[matg], gb, H, us, 0, FX, nullptr, nullptr, nullptr, din, s_red);
    psync(my, peer, ep);                                               // (c) B.x0 (rh) all rows
    {
        const int a0 = SPL ? UNITS : 0;       // SPL: rh cols only (x-part served by A)
        sp_apply<FP,STRR,true >(xkB, xhB, xlB, 0,  FP,   a0, s_ent, s_rp, rbeg, rend);
        psync(my, peer, ep);                                           // (d) B.x1 all rows
        sp_apply<FP,STRR,false>(xkB, xhB, xlB, FP, 2*FP, a0, s_ent, s_rp, rbeg, rend);
    }
    __syncthreads();                                                   // own rows only below
    if (SPL){
        gemm_chunk<4,4,64,FP,STRR,true >(rbeg,       rend, xhA, xlA, xhB, xlB, xkB, xhB, xlB,
            g_wph[matc], g_wpl[matc], cb, H, us, epi_cand, FX, pW, pb, out_t, din, s_red);
        gemm_chunk<2,8,64,FP,STRR,true >(rbeg + 128, rend, xhA, xlA, xhB, xlB, xkB, xhB, xlB,
            g_wph[matc], g_wpl[matc], cb, H, us, epi_cand, FX, pW, pb, out_t, din, s_red);
    } else {
        gemm_chunk<4,4,64,FP,STRR,false>(rbeg,       rend, xhB, xlB, xhB, xlB, xkB, xhB, xlB,
            g_wph[matc], g_wpl[matc], cb, H, us, epi_cand, FX, pW, pb, out_t, din, s_red);
        gemm_chunk<2,8,64,FP,STRR,false>(rbeg + 128, rend, xhB, xlB, xhB, xlB, xkB, xhB, xlB,
            g_wph[matc], g_wpl[matc], cb, H, us, epi_cand, FX, pW, pb, out_t, din, s_red);
    }
    psync(my, peer, ep);      // (e) CELL END: full psync (R12-proven) across stride flip
}

// ---------------- the whole network + setup in ONE kernel ----------------
__global__ void __launch_bounds__(NTH, 1)
dcrnn_all(const float* __restrict__ inputs, const float* __restrict__ S,
          const float* e0gW, const float* e1gW, const float* d0gW, const float* d1gW,
          const float* e0cW, const float* e1cW, const float* d0cW, const float* d1cW,
          const float* e0gb, const float* e0cb,
          const float* e1gb, const float* e1cb,
          const float* d0gb, const float* d0cb,
          const float* d1gb, const float* d1cb,
          const float* pW, const float* pb, float* __restrict__ out)
{
    __shared__ ull s_ent[MAXE];
    __shared__ int s_rp[NNODES+1];
    __shared__ float s_red[128*8];

    const int b = blockIdx.x >> 1, rank = blockIdx.x & 1;
    const int rbeg = rank ? SPLIT : 0;
    const int rend = rank ? NNODES : SPLIT;
    const int tid = threadIdx.x, lane = tid & 31, wid = tid >> 5;
    volatile unsigned* my   = &g_slot[b][rank];
    volatile unsigned* peer = &g_slot[b][rank ^ 1];
    unsigned ep = 0;
    if (tid == 0) ep = *my;          // replay-safe baseline (self-written slot only)

    // ---- in-kernel CSR build from dense S (warp-ballot, smem-resident) ----
    int* s_cnt = (int*)s_red;        // alias during setup only
    for (int m = wid; m < NNODES; m += NWARPS){
        int c = 0;
        for (int c0 = 0; c0 < NNODES; c0 += 32){
            int col = c0 + lane;
            float v = (col < NNODES) ? S[m*NNODES + col] : 0.f;
            c += __popc(__ballot_sync(0xffffffffu, v != 0.f));
        }
        if (lane == 0) s_cnt[m] = c;
    }
    __syncthreads();
    if (tid == 0){
        int acc = 0;
        for (int m = 0; m < NNODES; m++){ int c = s_cnt[m]; s_rp[m] = acc; acc += c; }
        s_rp[NNODES] = acc;
    }
    __syncthreads();
    for (int m = wid; m < NNODES; m += NWARPS){
        int p = s_rp[m];
        for (int c0 = 0; c0 < NNODES; c0 += 32){
            int col = c0 + lane;
            float v = (col < NNODES) ? S[m*NNODES + col] : 0.f;
            unsigned msk = __ballot_sync(0xffffffffu, v != 0.f);
            if (v != 0.f)
                s_ent[p + __popc(msk & ((1u<<lane)-1))] =
                    ((ull)__float_as_uint(v) << 32) | (unsigned)col;
            p += __popc(msk);
        }
    }

    // ---- in-kernel weight prep: rank0 packs gate mats 0..3, rank1 cand mats 4..7.
    //      Duplicate identical writes across CTAs of same rank (benign); peer half
    //      becomes visible via the full-fence psyncs before its first GEMM use. ----
    {
        const float* Ws[8] = {e0gW, e1gW, d0gW, d1gW, e0cW, e1cW, d0cW, d1cW};
        const int Fs[8]  = {66, 128, 65, 128, 66, 128, 65, 128};
        const int FPs[8] = {68, 128, 68, 128, 68, 128, 68, 128};
        const int ONs[8] = {128, 128, 128, 128, 64, 64, 64, 64};
        int m0 = rank ? 4 : 0;
        for (int mat = m0; mat < m0 + 4; mat++){
            const float* W = Ws[mat];
            int F = Fs[mat], FP = FPs[mat], ONUM = ONs[mat];
            int F3P = 3*FP, NKT = (F3P + 15)/16, NB8 = ONUM/8;
            int total = NB8*NKT*64;
            for (int idx = tid; idx < total; idx += NTH){
                int reg = idx & 1, ln = (idx >> 1) & 31;
                int t2 = idx >> 6; int kt = t2 % NKT, nb8 = t2 / NKT;
                int gg = ln >> 2, qq = ln & 3;
                int n  = nb8*8 + gg;
                int k0 = kt*16 + qq*2 + reg*8;
                float w0 = wmod(W, F, FP, ONUM, k0,     n);
                float w1 = wmod(W, F, FP, ONUM, k0 + 1, n);
                bf16 h0,l0,h1,l1; bfsplit(w0,h0,l0); bfsplit(w1,h1,l1);
                g_wph[mat][idx] = (unsigned)__bfloat16_as_ushort(h0) | ((unsigned)__bfloat16_as_ushort(h1) << 16);
                g_wpl[mat][idx] = (unsigned)__bfloat16_as_ushort(l0) | ((unsigned)__bfloat16_as_ushort(l1) << 16);
            }
        }
    }

    // ---- zero own state ----
    float* h0  = g_h0 + b*NNODES*UNITS;
    float* h1  = g_h1 + b*NNODES*UNITS;
    float* din = g_din + b*NNODES;
    for (int i = tid; i < (rend - rbeg)*UNITS; i += NTH)
        { h0[rbeg*UNITS + i] = 0.f; h1[rbeg*UNITS + i] = 0.f; }
    for (int i = tid; i < rend - rbeg; i += NTH) din[rbeg + i] = 0.f;
    __syncthreads();   // own-CTA setup visible (global via own L1; smem via sync)

    // ---- encoder ----
    for (int t = 0; t < TSTEPS; t++){
        const float* xin = inputs + ((size_t)t*BATCH + b)*NNODES*DIN;
        cell_run<2,66,68,208>(b, rbeg, rend, xin, h0, 0, 4, e0gb, e0cb, 1,
                              nullptr, nullptr, nullptr, my, peer, ep, s_ent, s_rp, s_red);
        cell_run<64,128,128,384>(b, rbeg, rend, h0, h1, 1, 5, e1gb, e1cb, 1,
                              nullptr, nullptr, nullptr, my, peer, ep, s_ent, s_rp, s_red);
    }
    // ---- decoder ----
    for (int t = 0; t < HORIZON; t++){
        cell_run<1,65,68,208>(b, rbeg, rend, din, h0, 2, 6, d0gb, d0cb, 1,
                              nullptr, nullptr, nullptr, my, peer, ep, s_ent, s_rp, s_red);
        cell_run<64,128,128,384>(b, rbeg, rend, h0, h1, 3, 7, d1gb, d1cb, 2,
                              pW, pb, out + ((size_t)t*BATCH + b)*NNODES,
                              my, peer, ep, s_ent, s_rp, s_red);
    }
}

extern "C" void kernel_launch(void* const* d_in, const int* in_sizes, int n_in,
                              void* d_out, int out_size)
{
    const float* inputs  = (const float*)d_in[0];
    const float* support = (const float*)d_in[1];
    const float* e0gW = (const float*)d_in[2];  const float* e0gb = (const float*)d_in[3];
    const float* e0cW = (const float*)d_in[4];  const float* e0cb = (const float*)d_in[5];
    const float* e1gW = (const float*)d_in[6];  const float* e1gb = (const float*)d_in[7];
    const float* e1cW = (const float*)d_in[8];  const float* e1cb = (const float*)d_in[9];
    const float* d0gW = (const float*)d_in[10]; const float* d0gb = (const float*)d_in[11];
    const float* d0cW = (const float*)d_in[12]; const float* d0cb = (const float*)d_in[13];
    const float* d1gW = (const float*)d_in[14]; const float* d1gb = (const float*)d_in[15];
    const float* d1cW = (const float*)d_in[16]; const float* d1cb = (const float*)d_in[17];
    const float* pW   = (const float*)d_in[18]; const float* pb   = (const float*)d_in[19];
    float* out = (float*)d_out;

    // ONE launch per call: every stream launch is the main kernel -> ncu must capture it.
    dcrnn_all<<<2*BATCH, NTH>>>(inputs, support,
        e0gW, e1gW, d0gW, d1gW, e0cW, e1cW, d0cW, d1cW,
        e0gb, e0cb, e1gb, e1cb, d0gb, d0cb, d1gb, d1cb,
        pW, pb, out);
}